// round 10
// baseline (speedup 1.0000x reference)
#include <cuda_runtime.h>
#include <cuda_fp16.h>

// Problem constants
#define NB 2
#define NC 128
#define NS 2048
#define MPX 65536                // Nz*Nx pixels per batch
#define NKK 4

#define THREADS 256
#define PXT 4                    // pixels per thread
#define TILE_PX (THREADS * PXT)  // 1024 pixels per CTA
#define TILES (MPX / TILE_PX)    // 64 tiles per batch

#define SPLIT 4
#define CPC (NC / SPLIT)         // 32 channels per CTA

#define NBUF 3                   // triple buffer
#define CH_BYTES (NS * NKK * 2)  // 16384 B per fp16 channel row

#define SMEM_PR_OFF   (NBUF * CH_BYTES)
#define SMEM_MBAR_OFF (SMEM_PR_OFF + CPC * 3 * 4)
#define SMEM_BYTES    (SMEM_MBAR_OFF + NBUF * 8)

// Static device scratch (no allocations allowed)
__device__ __half g_rf16[(size_t)NB * NC * NS * NKK];           // 4.2 MB

__device__ __forceinline__ unsigned smem_u32(const void* p) {
    unsigned a;
    asm("{ .reg .u64 t; cvta.to.shared.u64 t, %1; cvt.u32.u64 %0, t; }"
        : "=r"(a) : "l"(p));
    return a;
}
__device__ __forceinline__ void mbar_init(unsigned mbar, unsigned count) {
    asm volatile("mbarrier.init.shared.b64 [%0], %1;" :: "r"(mbar), "r"(count) : "memory");
}
__device__ __forceinline__ void mbar_expect_tx(unsigned mbar, unsigned bytes) {
    asm volatile("mbarrier.arrive.expect_tx.shared.b64 _, [%0], %1;"
                 :: "r"(mbar), "r"(bytes) : "memory");
}
__device__ __forceinline__ void mbar_wait_parity(unsigned mbar, unsigned parity) {
    unsigned done;
    asm volatile(
        "{\n\t"
        ".reg .pred p;\n\t"
        "mbarrier.try_wait.parity.acquire.cta.shared::cta.b64 p, [%1], %2;\n\t"
        "selp.b32 %0, 1, 0, p;\n\t"
        "}"
        : "=r"(done) : "r"(mbar), "r"(parity) : "memory");
    if (!done) {
        asm volatile(
            "{\n\t"
            ".reg .pred P1;\n\t"
            "WAIT_LOOP_%=:\n\t"
            "mbarrier.try_wait.parity.acquire.cta.shared::cta.b64 P1, [%0], %1, 0x989680;\n\t"
            "@P1 bra.uni WAIT_DONE_%=;\n\t"
            "bra.uni WAIT_LOOP_%=;\n\t"
            "WAIT_DONE_%=:\n\t"
            "}"
            :: "r"(mbar), "r"(parity) : "memory");
    }
}
__device__ __forceinline__ void bulk_copy_g2s(unsigned dst_smem, const void* src,
                                              unsigned bytes, unsigned mbar) {
    asm volatile(
        "cp.async.bulk.shared::cta.global.mbarrier::complete_tx::bytes [%0], [%1], %2, [%3];"
        :: "r"(dst_smem), "l"(src), "r"(bytes), "r"(mbar) : "memory");
}
__device__ __forceinline__ void fence_async_shared() {
    asm volatile("fence.proxy.async.shared::cta;" ::: "memory");
}
__device__ __forceinline__ float fast_sqrtf(float x) {
    float r;
    asm("sqrt.approx.f32 %0, %1;" : "=f"(r) : "f"(x));
    return r;
}

// ---------------------------------------------------------------------------
// Kernel 1: convert rf fp32 -> fp16 scratch. 2 rows per thread.
// ---------------------------------------------------------------------------
__global__ void convert_rf_kernel(const float4* __restrict__ rf4) {
    int t = blockIdx.x * blockDim.x + threadIdx.x;   // NB*NC*NS/2 threads
    int idx = t * 2;
    float4 v0 = rf4[idx + 0];
    float4 v1 = rf4[idx + 1];
    uint4 o;
    __half2 h;
    h = __floats2half2_rn(v0.x, v0.y); o.x = *reinterpret_cast<unsigned*>(&h);
    h = __floats2half2_rn(v0.z, v0.w); o.y = *reinterpret_cast<unsigned*>(&h);
    h = __floats2half2_rn(v1.x, v1.y); o.z = *reinterpret_cast<unsigned*>(&h);
    h = __floats2half2_rn(v1.z, v1.w); o.w = *reinterpret_cast<unsigned*>(&h);
    reinterpret_cast<uint4*>(g_rf16)[t] = o;
}

// ---------------------------------------------------------------------------
// Kernel 2: zero the output (harness poisons it to 0xAA before timing).
// ---------------------------------------------------------------------------
__global__ void zero_out_kernel(float4* __restrict__ out4) {
    int i = blockIdx.x * blockDim.x + threadIdx.x;   // NB*MPX float4s
    out4[i] = make_float4(0.f, 0.f, 0.f, 0.f);
}

// ---------------------------------------------------------------------------
// Kernel 3: main DAS beamform; channel-slice partials accumulated straight
// into out via float4 atomicAdd (RED.128). TMA bulk fill, triple-buffered.
// ---------------------------------------------------------------------------
extern __shared__ char smem_raw[];

__global__ __launch_bounds__(THREADS, 4)
void das_beamform_kernel(const float* __restrict__ g,
                         const float* __restrict__ pr,
                         const float* __restrict__ p,
                         float4* __restrict__ out4)
{
    uint2* sbuf = reinterpret_cast<uint2*>(smem_raw);                  // [NBUF][NS]
    float* s_pr = reinterpret_cast<float*>(smem_raw + SMEM_PR_OFF);
    const unsigned mbar0 = smem_u32(smem_raw + SMEM_MBAR_OFF);         // 3 mbarriers

    const int b     = blockIdx.y;
    const int sp    = blockIdx.z;
    const int tile0 = blockIdx.x * TILE_PX;
    const int tid   = threadIdx.x;
    const int c0    = sp * CPC;

    const float c0v = p[b * 4 + 0];
    const float fs  = p[b * 4 + 1];
    const float t0  = p[b * 4 + 2];
    const float scale = fs / c0v;
    const float toff  = t0 * scale;

    // Cache this slice's receiver positions
    if (tid < CPC * 3)
        s_pr[tid] = pr[((size_t)b * NC + c0) * 3 + tid];

    // fp16 rf channel rows for this (batch, slice)
    const char* rfb = reinterpret_cast<const char*>(g_rf16) +
                      ((size_t)b * NC + c0) * CH_BYTES;

    // Init mbarriers and issue preload of channels 0,1 (thread 0)
    if (tid == 0) {
        #pragma unroll
        for (int i = 0; i < NBUF; i++)
            mbar_init(mbar0 + i * 8, 1);
        fence_async_shared();
        #pragma unroll
        for (int pc = 0; pc < 2; pc++) {
            mbar_expect_tx(mbar0 + pc * 8, CH_BYTES);
            bulk_copy_g2s(smem_u32(sbuf) + pc * CH_BYTES,
                          rfb + (size_t)pc * CH_BYTES, CH_BYTES, mbar0 + pc * 8);
        }
    }

    float gx[PXT], gy[PXT], gz[PXT], base[PXT];
    float4 acc[PXT];
#pragma unroll
    for (int q = 0; q < PXT; q++) {
        int m = tile0 + tid + q * THREADS;
        const float* gp = g + ((size_t)b * MPX + m) * 3;
        gx[q] = gp[0];
        gy[q] = gp[1];
        gz[q] = gp[2];
        base[q] = fmaf(scale, gz[q], toff);
        acc[q] = make_float4(0.f, 0.f, 0.f, 0.f);
    }

    for (int cc = 0; cc < CPC; cc++) {
        // All threads done with channel cc-1 => buffer (cc+2)%NBUF is free
        __syncthreads();

        if (tid == 0 && cc + 2 < CPC) {
            int nb = (cc + 2) % NBUF;
            fence_async_shared();
            mbar_expect_tx(mbar0 + nb * 8, CH_BYTES);
            bulk_copy_g2s(smem_u32(sbuf) + nb * CH_BYTES,
                          rfb + (size_t)(cc + 2) * CH_BYTES, CH_BYTES, mbar0 + nb * 8);
        }

        // Wait for channel cc's buffer
        mbar_wait_parity(mbar0 + (cc % NBUF) * 8, (cc / NBUF) & 1);

        const uint2* buf = sbuf + (cc % NBUF) * NS;
        const float prx = s_pr[cc * 3 + 0];
        const float pry = s_pr[cc * 3 + 1];
        const float prz = s_pr[cc * 3 + 2];

#pragma unroll
        for (int q = 0; q < PXT; q++) {
            float dx = gx[q] - prx;
            float dy = gy[q] - pry;
            float dz = gz[q] - prz;
            float d2 = fmaf(dx, dx, fmaf(dy, dy, dz * dz));
            float dr = fast_sqrtf(d2);
            float s  = fmaf(scale, dr, base[q]);
            s = fminf(fmaxf(s, 0.0f), (float)(NS - 1));
            int i0 = (int)s;
            i0 = min(i0, NS - 2);
            float w = s - (float)i0;

            uint2 r0 = buf[i0];
            uint2 r1 = buf[i0 + 1];
            float2 a0 = __half22float2(*reinterpret_cast<__half2*>(&r0.x));
            float2 b0 = __half22float2(*reinterpret_cast<__half2*>(&r0.y));
            float2 a1 = __half22float2(*reinterpret_cast<__half2*>(&r1.x));
            float2 b1 = __half22float2(*reinterpret_cast<__half2*>(&r1.y));

            acc[q].x = fmaf(w, a1.x - a0.x, acc[q].x + a0.x);
            acc[q].y = fmaf(w, a1.y - a0.y, acc[q].y + a0.y);
            acc[q].z = fmaf(w, b1.x - b0.x, acc[q].z + b0.x);
            acc[q].w = fmaf(w, b1.y - b0.y, acc[q].w + b0.y);
        }
    }

    // Accumulate partials straight into the output (RED.128)
    float4* op = out4 + (size_t)b * MPX + tile0;
#pragma unroll
    for (int q = 0; q < PXT; q++)
        atomicAdd(&op[tid + q * THREADS], acc[q]);
}

extern "C" void kernel_launch(void* const* d_in, const int* in_sizes, int n_in,
                              void* d_out, int out_size)
{
    const float* rf = (const float*)d_in[0];   // [B, Nc, Ns, K]
    const float* g  = (const float*)d_in[1];   // [B, Nz, Nx, 3]
    const float* pr = (const float*)d_in[2];   // [B, Nc, 3]
    const float* p  = (const float*)d_in[3];   // [B, 4]
    float4* out4 = (float4*)d_out;             // [B, Nz, Nx, K]

    cudaFuncSetAttribute(das_beamform_kernel,
                         cudaFuncAttributeMaxDynamicSharedMemorySize, SMEM_BYTES);

    // 1) convert rf to fp16 scratch
    int rows = NB * NC * NS;   // 524288
    convert_rf_kernel<<<rows / 2 / 256, 256>>>((const float4*)rf);

    // 2) zero output (independent of convert; same stream ordering is fine)
    int n4 = NB * MPX;         // 131072 float4s
    zero_out_kernel<<<n4 / 256, 256>>>(out4);

    // 3) beamform per (tile, batch, channel-slice), atomic-accumulate into out
    dim3 grid(TILES, NB, SPLIT);
    das_beamform_kernel<<<grid, THREADS, SMEM_BYTES>>>(g, pr, p, out4);
}

// round 11
// speedup vs baseline: 1.2928x; 1.2928x over previous
#include <cuda_runtime.h>
#include <cuda_fp16.h>

// Problem constants
#define NB 2
#define NC 128
#define NS 2048
#define MPX 65536                // Nz*Nx pixels per batch
#define NKK 4

#define THREADS 1024
#define PXT 4                    // pixels per thread
#define TILE_PX (THREADS * PXT)  // 4096 pixels per CTA
#define TILES (MPX / TILE_PX)    // 16 tiles per batch

#define SPLIT 4
#define CPC (NC / SPLIT)         // 32 channels per CTA

#define NBUF 3                   // triple buffer
#define CH_BYTES (NS * NKK * 2)  // 16384 B per fp16 channel row

#define SMEM_PR_OFF   (NBUF * CH_BYTES)
#define SMEM_MBAR_OFF (SMEM_PR_OFF + CPC * 3 * 4)
#define SMEM_BYTES    (SMEM_MBAR_OFF + NBUF * 8)

// Static device scratch (no allocations allowed)
__device__ __half g_rf16[(size_t)NB * NC * NS * NKK];           // 4.2 MB
__device__ float  g_part[(size_t)SPLIT * NB * MPX * NKK];       // 8.4 MB

__device__ __forceinline__ unsigned smem_u32(const void* p) {
    unsigned a;
    asm("{ .reg .u64 t; cvta.to.shared.u64 t, %1; cvt.u32.u64 %0, t; }"
        : "=r"(a) : "l"(p));
    return a;
}
__device__ __forceinline__ void mbar_init(unsigned mbar, unsigned count) {
    asm volatile("mbarrier.init.shared.b64 [%0], %1;" :: "r"(mbar), "r"(count) : "memory");
}
__device__ __forceinline__ void mbar_expect_tx(unsigned mbar, unsigned bytes) {
    asm volatile("mbarrier.arrive.expect_tx.shared.b64 _, [%0], %1;"
                 :: "r"(mbar), "r"(bytes) : "memory");
}
__device__ __forceinline__ void mbar_wait_parity(unsigned mbar, unsigned parity) {
    unsigned done;
    asm volatile(
        "{\n\t"
        ".reg .pred p;\n\t"
        "mbarrier.try_wait.parity.acquire.cta.shared::cta.b64 p, [%1], %2;\n\t"
        "selp.b32 %0, 1, 0, p;\n\t"
        "}"
        : "=r"(done) : "r"(mbar), "r"(parity) : "memory");
    if (!done) {
        asm volatile(
            "{\n\t"
            ".reg .pred P1;\n\t"
            "WAIT_LOOP_%=:\n\t"
            "mbarrier.try_wait.parity.acquire.cta.shared::cta.b64 P1, [%0], %1, 0x989680;\n\t"
            "@P1 bra.uni WAIT_DONE_%=;\n\t"
            "bra.uni WAIT_LOOP_%=;\n\t"
            "WAIT_DONE_%=:\n\t"
            "}"
            :: "r"(mbar), "r"(parity) : "memory");
    }
}
__device__ __forceinline__ void bulk_copy_g2s(unsigned dst_smem, const void* src,
                                              unsigned bytes, unsigned mbar) {
    asm volatile(
        "cp.async.bulk.shared::cta.global.mbarrier::complete_tx::bytes [%0], [%1], %2, [%3];"
        :: "r"(dst_smem), "l"(src), "r"(bytes), "r"(mbar) : "memory");
}
__device__ __forceinline__ void fence_async_shared() {
    asm volatile("fence.proxy.async.shared::cta;" ::: "memory");
}
__device__ __forceinline__ float fast_sqrtf(float x) {
    float r;
    asm("sqrt.approx.f32 %0, %1;" : "=f"(r) : "f"(x));
    return r;
}

// ---------------------------------------------------------------------------
// Kernel 1: convert rf fp32 -> fp16 scratch. 2 rows per thread.
// ---------------------------------------------------------------------------
__global__ void convert_rf_kernel(const float4* __restrict__ rf4) {
    int t = blockIdx.x * blockDim.x + threadIdx.x;   // NB*NC*NS/2 threads
    int idx = t * 2;
    float4 v0 = rf4[idx + 0];
    float4 v1 = rf4[idx + 1];
    uint4 o;
    __half2 h;
    h = __floats2half2_rn(v0.x, v0.y); o.x = *reinterpret_cast<unsigned*>(&h);
    h = __floats2half2_rn(v0.z, v0.w); o.y = *reinterpret_cast<unsigned*>(&h);
    h = __floats2half2_rn(v1.x, v1.y); o.z = *reinterpret_cast<unsigned*>(&h);
    h = __floats2half2_rn(v1.z, v1.w); o.w = *reinterpret_cast<unsigned*>(&h);
    reinterpret_cast<uint4*>(g_rf16)[t] = o;
}

// ---------------------------------------------------------------------------
// Kernel 2: main DAS beamform over a channel slice, writes partial sums.
// TMA bulk fill (one 16KB copy per channel), triple-buffered.
// ---------------------------------------------------------------------------
extern __shared__ char smem_raw[];

__global__ __launch_bounds__(THREADS, 1)
void das_beamform_kernel(const float* __restrict__ g,
                         const float* __restrict__ pr,
                         const float* __restrict__ p)
{
    uint2* sbuf = reinterpret_cast<uint2*>(smem_raw);                  // [NBUF][NS]
    float* s_pr = reinterpret_cast<float*>(smem_raw + SMEM_PR_OFF);
    const unsigned mbar0 = smem_u32(smem_raw + SMEM_MBAR_OFF);         // 3 mbarriers

    const int b     = blockIdx.y;
    const int sp    = blockIdx.z;
    const int tile0 = blockIdx.x * TILE_PX;
    const int tid   = threadIdx.x;
    const int c0    = sp * CPC;

    const float c0v = p[b * 4 + 0];
    const float fs  = p[b * 4 + 1];
    const float t0  = p[b * 4 + 2];
    const float scale = fs / c0v;
    const float toff  = t0 * scale;

    // Cache this slice's receiver positions
    if (tid < CPC * 3)
        s_pr[tid] = pr[((size_t)b * NC + c0) * 3 + tid];

    // fp16 rf channel rows for this (batch, slice)
    const char* rfb = reinterpret_cast<const char*>(g_rf16) +
                      ((size_t)b * NC + c0) * CH_BYTES;

    // Init mbarriers and issue preload of channels 0,1 (thread 0)
    if (tid == 0) {
        #pragma unroll
        for (int i = 0; i < NBUF; i++)
            mbar_init(mbar0 + i * 8, 1);
        fence_async_shared();
        #pragma unroll
        for (int pc = 0; pc < 2; pc++) {
            mbar_expect_tx(mbar0 + pc * 8, CH_BYTES);
            bulk_copy_g2s(smem_u32(sbuf) + pc * CH_BYTES,
                          rfb + (size_t)pc * CH_BYTES, CH_BYTES, mbar0 + pc * 8);
        }
    }

    float gx[PXT], gy[PXT], gz[PXT], base[PXT];
    float4 acc[PXT];
#pragma unroll
    for (int q = 0; q < PXT; q++) {
        int m = tile0 + tid + q * THREADS;
        const float* gp = g + ((size_t)b * MPX + m) * 3;
        gx[q] = gp[0];
        gy[q] = gp[1];
        gz[q] = gp[2];
        base[q] = fmaf(scale, gz[q], toff);
        acc[q] = make_float4(0.f, 0.f, 0.f, 0.f);
    }

    for (int cc = 0; cc < CPC; cc++) {
        // All threads done with channel cc-1 => buffer (cc+2)%NBUF is free
        __syncthreads();

        if (tid == 0 && cc + 2 < CPC) {
            int nb = (cc + 2) % NBUF;
            fence_async_shared();
            mbar_expect_tx(mbar0 + nb * 8, CH_BYTES);
            bulk_copy_g2s(smem_u32(sbuf) + nb * CH_BYTES,
                          rfb + (size_t)(cc + 2) * CH_BYTES, CH_BYTES, mbar0 + nb * 8);
        }

        // Wait for channel cc's buffer
        mbar_wait_parity(mbar0 + (cc % NBUF) * 8, (cc / NBUF) & 1);

        const uint2* buf = sbuf + (cc % NBUF) * NS;
        const float prx = s_pr[cc * 3 + 0];
        const float pry = s_pr[cc * 3 + 1];
        const float prz = s_pr[cc * 3 + 2];

#pragma unroll
        for (int q = 0; q < PXT; q++) {
            float dx = gx[q] - prx;
            float dy = gy[q] - pry;
            float dz = gz[q] - prz;
            float d2 = fmaf(dx, dx, fmaf(dy, dy, dz * dz));
            float dr = fast_sqrtf(d2);
            float s  = fmaf(scale, dr, base[q]);
            s = fminf(fmaxf(s, 0.0f), (float)(NS - 1));
            int i0 = (int)s;
            i0 = min(i0, NS - 2);
            float w = s - (float)i0;

            uint2 r0 = buf[i0];
            uint2 r1 = buf[i0 + 1];
            float2 a0 = __half22float2(*reinterpret_cast<__half2*>(&r0.x));
            float2 b0 = __half22float2(*reinterpret_cast<__half2*>(&r0.y));
            float2 a1 = __half22float2(*reinterpret_cast<__half2*>(&r1.x));
            float2 b1 = __half22float2(*reinterpret_cast<__half2*>(&r1.y));

            acc[q].x = fmaf(w, a1.x - a0.x, acc[q].x + a0.x);
            acc[q].y = fmaf(w, a1.y - a0.y, acc[q].y + a0.y);
            acc[q].z = fmaf(w, b1.x - b0.x, acc[q].z + b0.x);
            acc[q].w = fmaf(w, b1.y - b0.y, acc[q].w + b0.y);
        }
    }

    float4* pp = reinterpret_cast<float4*>(g_part) +
                 ((size_t)sp * NB + b) * MPX + tile0;
#pragma unroll
    for (int q = 0; q < PXT; q++)
        pp[tid + q * THREADS] = acc[q];
}

// ---------------------------------------------------------------------------
// Kernel 3: reduce SPLIT partials into the output.
// ---------------------------------------------------------------------------
__global__ void reduce_kernel(float4* __restrict__ out4) {
    int i = blockIdx.x * blockDim.x + threadIdx.x;   // over NB*MPX float4s
    const size_t stride = (size_t)NB * MPX;
    const float4* pp = reinterpret_cast<const float4*>(g_part);
    float4 a = pp[i];
    float4 b = pp[i + stride];
    float4 c = pp[i + 2 * stride];
    float4 d = pp[i + 3 * stride];
    float4 r;
    r.x = (a.x + b.x) + (c.x + d.x);
    r.y = (a.y + b.y) + (c.y + d.y);
    r.z = (a.z + b.z) + (c.z + d.z);
    r.w = (a.w + b.w) + (c.w + d.w);
    out4[i] = r;
}

extern "C" void kernel_launch(void* const* d_in, const int* in_sizes, int n_in,
                              void* d_out, int out_size)
{
    const float* rf = (const float*)d_in[0];   // [B, Nc, Ns, K]
    const float* g  = (const float*)d_in[1];   // [B, Nz, Nx, 3]
    const float* pr = (const float*)d_in[2];   // [B, Nc, 3]
    const float* p  = (const float*)d_in[3];   // [B, 4]
    float* out = (float*)d_out;                // [B, Nz, Nx, K]

    cudaFuncSetAttribute(das_beamform_kernel,
                         cudaFuncAttributeMaxDynamicSharedMemorySize, SMEM_BYTES);

    // 1) convert rf to fp16 scratch
    int rows = NB * NC * NS;   // 524288
    convert_rf_kernel<<<rows / 2 / 256, 256>>>((const float4*)rf);

    // 2) beamform per (tile, batch, channel-slice)
    dim3 grid(TILES, NB, SPLIT);
    das_beamform_kernel<<<grid, THREADS, SMEM_BYTES>>>(g, pr, p);

    // 3) reduce partials
    int n4 = NB * MPX;         // 131072 float4s
    reduce_kernel<<<n4 / 256, 256>>>((float4*)out);
}

// round 12
// speedup vs baseline: 1.4513x; 1.1226x over previous
#include <cuda_runtime.h>
#include <cuda_fp16.h>

// Problem constants
#define NB 2
#define NC 128
#define NS 2048
#define MPX 65536                // Nz*Nx pixels per batch
#define NKK 4

#define THREADS 256
#define PXT 4                    // pixels per thread
#define TILE_PX (THREADS * PXT)  // 1024 pixels per CTA
#define TILES (MPX / TILE_PX)    // 64 tiles per batch

#define SPLIT 4
#define CPC (NC / SPLIT)         // 32 channels per CTA

#define NBUF 3                   // triple buffer
#define CH_BYTES (NS * NKK * 2)  // 16384 B per fp16 channel row

#define SMEM_PR_OFF   (NBUF * CH_BYTES)
#define SMEM_MBAR_OFF (SMEM_PR_OFF + CPC * 3 * 4)
#define SMEM_BYTES    (SMEM_MBAR_OFF + NBUF * 8)

// Static device scratch (no allocations allowed)
__device__ __half g_rf16[(size_t)NB * NC * NS * NKK];           // 4.2 MB
__device__ float  g_part[(size_t)SPLIT * NB * MPX * NKK];       // 8.4 MB

__device__ __forceinline__ unsigned smem_u32(const void* p) {
    unsigned a;
    asm("{ .reg .u64 t; cvta.to.shared.u64 t, %1; cvt.u32.u64 %0, t; }"
        : "=r"(a) : "l"(p));
    return a;
}
__device__ __forceinline__ void mbar_init(unsigned mbar, unsigned count) {
    asm volatile("mbarrier.init.shared.b64 [%0], %1;" :: "r"(mbar), "r"(count) : "memory");
}
__device__ __forceinline__ void mbar_expect_tx(unsigned mbar, unsigned bytes) {
    asm volatile("mbarrier.arrive.expect_tx.shared.b64 _, [%0], %1;"
                 :: "r"(mbar), "r"(bytes) : "memory");
}
__device__ __forceinline__ void mbar_wait_parity(unsigned mbar, unsigned parity) {
    unsigned done;
    asm volatile(
        "{\n\t"
        ".reg .pred p;\n\t"
        "mbarrier.try_wait.parity.acquire.cta.shared::cta.b64 p, [%1], %2;\n\t"
        "selp.b32 %0, 1, 0, p;\n\t"
        "}"
        : "=r"(done) : "r"(mbar), "r"(parity) : "memory");
    if (!done) {
        asm volatile(
            "{\n\t"
            ".reg .pred P1;\n\t"
            "WAIT_LOOP_%=:\n\t"
            "mbarrier.try_wait.parity.acquire.cta.shared::cta.b64 P1, [%0], %1, 0x989680;\n\t"
            "@P1 bra.uni WAIT_DONE_%=;\n\t"
            "bra.uni WAIT_LOOP_%=;\n\t"
            "WAIT_DONE_%=:\n\t"
            "}"
            :: "r"(mbar), "r"(parity) : "memory");
    }
}
__device__ __forceinline__ void bulk_copy_g2s(unsigned dst_smem, const void* src,
                                              unsigned bytes, unsigned mbar) {
    asm volatile(
        "cp.async.bulk.shared::cta.global.mbarrier::complete_tx::bytes [%0], [%1], %2, [%3];"
        :: "r"(dst_smem), "l"(src), "r"(bytes), "r"(mbar) : "memory");
}
__device__ __forceinline__ void fence_async_shared() {
    asm volatile("fence.proxy.async.shared::cta;" ::: "memory");
}

// sqrt with NO MUFU: bit-hack rsqrt seed + 3 Newton iterations (FMA/ALU only).
// Seed rel err ~3.4e-2; after 3 Newtons converged to fp32 rounding (~1e-7).
__device__ __forceinline__ float sqrt_nomufu(float x) {
    float xh = 0.5f * x;
    int i = __float_as_int(x);
    i = 0x5f375a86 - (i >> 1);
    float y = __int_as_float(i);
    y = y * fmaf(-xh, y * y, 1.5f);
    y = y * fmaf(-xh, y * y, 1.5f);
    y = y * fmaf(-xh, y * y, 1.5f);
    return x * y;   // x * rsqrt(x) = sqrt(x); exact 0 for x=0
}

// ---------------------------------------------------------------------------
// Kernel 1: convert rf fp32 -> fp16 scratch. 2 rows per thread.
// ---------------------------------------------------------------------------
__global__ void convert_rf_kernel(const float4* __restrict__ rf4) {
    int t = blockIdx.x * blockDim.x + threadIdx.x;   // NB*NC*NS/2 threads
    int idx = t * 2;
    float4 v0 = rf4[idx + 0];
    float4 v1 = rf4[idx + 1];
    uint4 o;
    __half2 h;
    h = __floats2half2_rn(v0.x, v0.y); o.x = *reinterpret_cast<unsigned*>(&h);
    h = __floats2half2_rn(v0.z, v0.w); o.y = *reinterpret_cast<unsigned*>(&h);
    h = __floats2half2_rn(v1.x, v1.y); o.z = *reinterpret_cast<unsigned*>(&h);
    h = __floats2half2_rn(v1.z, v1.w); o.w = *reinterpret_cast<unsigned*>(&h);
    reinterpret_cast<uint4*>(g_rf16)[t] = o;
}

// ---------------------------------------------------------------------------
// Kernel 2: main DAS beamform over a channel slice, writes partial sums.
// TMA bulk fill (one 16KB copy per channel), triple-buffered.
// ---------------------------------------------------------------------------
extern __shared__ char smem_raw[];

__global__ __launch_bounds__(THREADS, 4)
void das_beamform_kernel(const float* __restrict__ g,
                         const float* __restrict__ pr,
                         const float* __restrict__ p)
{
    uint2* sbuf = reinterpret_cast<uint2*>(smem_raw);                  // [NBUF][NS]
    float* s_pr = reinterpret_cast<float*>(smem_raw + SMEM_PR_OFF);
    const unsigned mbar0 = smem_u32(smem_raw + SMEM_MBAR_OFF);         // 3 mbarriers

    const int b     = blockIdx.y;
    const int sp    = blockIdx.z;
    const int tile0 = blockIdx.x * TILE_PX;
    const int tid   = threadIdx.x;
    const int c0    = sp * CPC;

    const float c0v = p[b * 4 + 0];
    const float fs  = p[b * 4 + 1];
    const float t0  = p[b * 4 + 2];
    const float scale = fs / c0v;
    const float toff  = t0 * scale;

    // Cache this slice's receiver positions
    if (tid < CPC * 3)
        s_pr[tid] = pr[((size_t)b * NC + c0) * 3 + tid];

    // fp16 rf channel rows for this (batch, slice)
    const char* rfb = reinterpret_cast<const char*>(g_rf16) +
                      ((size_t)b * NC + c0) * CH_BYTES;

    // Init mbarriers and issue preload of channels 0,1 (thread 0)
    if (tid == 0) {
        #pragma unroll
        for (int i = 0; i < NBUF; i++)
            mbar_init(mbar0 + i * 8, 1);
        fence_async_shared();
        #pragma unroll
        for (int pc = 0; pc < 2; pc++) {
            mbar_expect_tx(mbar0 + pc * 8, CH_BYTES);
            bulk_copy_g2s(smem_u32(sbuf) + pc * CH_BYTES,
                          rfb + (size_t)pc * CH_BYTES, CH_BYTES, mbar0 + pc * 8);
        }
    }

    float gx[PXT], gy[PXT], gz[PXT], base[PXT];
    float4 acc[PXT];
#pragma unroll
    for (int q = 0; q < PXT; q++) {
        int m = tile0 + tid + q * THREADS;
        const float* gp = g + ((size_t)b * MPX + m) * 3;
        gx[q] = gp[0];
        gy[q] = gp[1];
        gz[q] = gp[2];
        base[q] = fmaf(scale, gz[q], toff);
        acc[q] = make_float4(0.f, 0.f, 0.f, 0.f);
    }

    for (int cc = 0; cc < CPC; cc++) {
        // All threads done with channel cc-1 => buffer (cc+2)%NBUF is free
        __syncthreads();

        if (tid == 0 && cc + 2 < CPC) {
            int nb = (cc + 2) % NBUF;
            fence_async_shared();
            mbar_expect_tx(mbar0 + nb * 8, CH_BYTES);
            bulk_copy_g2s(smem_u32(sbuf) + nb * CH_BYTES,
                          rfb + (size_t)(cc + 2) * CH_BYTES, CH_BYTES, mbar0 + nb * 8);
        }

        // Wait for channel cc's buffer
        mbar_wait_parity(mbar0 + (cc % NBUF) * 8, (cc / NBUF) & 1);

        const uint2* buf = sbuf + (cc % NBUF) * NS;
        const float prx = s_pr[cc * 3 + 0];
        const float pry = s_pr[cc * 3 + 1];
        const float prz = s_pr[cc * 3 + 2];

#pragma unroll
        for (int q = 0; q < PXT; q++) {
            float dx = gx[q] - prx;
            float dy = gy[q] - pry;
            float dz = gz[q] - prz;
            float d2 = fmaf(dx, dx, fmaf(dy, dy, dz * dz));
            float dr = sqrt_nomufu(d2);
            float s  = fmaf(scale, dr, base[q]);
            s = fminf(fmaxf(s, 0.0f), (float)(NS - 1));
            int i0 = (int)s;
            i0 = min(i0, NS - 2);
            float w = s - (float)i0;

            uint2 r0 = buf[i0];
            uint2 r1 = buf[i0 + 1];
            float2 a0 = __half22float2(*reinterpret_cast<__half2*>(&r0.x));
            float2 b0 = __half22float2(*reinterpret_cast<__half2*>(&r0.y));
            float2 a1 = __half22float2(*reinterpret_cast<__half2*>(&r1.x));
            float2 b1 = __half22float2(*reinterpret_cast<__half2*>(&r1.y));

            acc[q].x = fmaf(w, a1.x - a0.x, acc[q].x + a0.x);
            acc[q].y = fmaf(w, a1.y - a0.y, acc[q].y + a0.y);
            acc[q].z = fmaf(w, b1.x - b0.x, acc[q].z + b0.x);
            acc[q].w = fmaf(w, b1.y - b0.y, acc[q].w + b0.y);
        }
    }

    float4* pp = reinterpret_cast<float4*>(g_part) +
                 ((size_t)sp * NB + b) * MPX + tile0;
#pragma unroll
    for (int q = 0; q < PXT; q++)
        pp[tid + q * THREADS] = acc[q];
}

// ---------------------------------------------------------------------------
// Kernel 3: reduce SPLIT partials into the output.
// ---------------------------------------------------------------------------
__global__ void reduce_kernel(float4* __restrict__ out4) {
    int i = blockIdx.x * blockDim.x + threadIdx.x;   // over NB*MPX float4s
    const size_t stride = (size_t)NB * MPX;
    const float4* pp = reinterpret_cast<const float4*>(g_part);
    float4 a = pp[i];
    float4 b = pp[i + stride];
    float4 c = pp[i + 2 * stride];
    float4 d = pp[i + 3 * stride];
    float4 r;
    r.x = (a.x + b.x) + (c.x + d.x);
    r.y = (a.y + b.y) + (c.y + d.y);
    r.z = (a.z + b.z) + (c.z + d.z);
    r.w = (a.w + b.w) + (c.w + d.w);
    out4[i] = r;
}

extern "C" void kernel_launch(void* const* d_in, const int* in_sizes, int n_in,
                              void* d_out, int out_size)
{
    const float* rf = (const float*)d_in[0];   // [B, Nc, Ns, K]
    const float* g  = (const float*)d_in[1];   // [B, Nz, Nx, 3]
    const float* pr = (const float*)d_in[2];   // [B, Nc, 3]
    const float* p  = (const float*)d_in[3];   // [B, 4]
    float* out = (float*)d_out;                // [B, Nz, Nx, K]

    cudaFuncSetAttribute(das_beamform_kernel,
                         cudaFuncAttributeMaxDynamicSharedMemorySize, SMEM_BYTES);

    // 1) convert rf to fp16 scratch
    int rows = NB * NC * NS;   // 524288
    convert_rf_kernel<<<rows / 2 / 256, 256>>>((const float4*)rf);

    // 2) beamform per (tile, batch, channel-slice)
    dim3 grid(TILES, NB, SPLIT);
    das_beamform_kernel<<<grid, THREADS, SMEM_BYTES>>>(g, pr, p);

    // 3) reduce partials
    int n4 = NB * MPX;         // 131072 float4s
    reduce_kernel<<<n4 / 256, 256>>>((float4*)out);
}

// round 14
// speedup vs baseline: 1.5228x; 1.0493x over previous
#include <cuda_runtime.h>
#include <cuda_fp16.h>

// Problem constants
#define NB 2
#define NC 128
#define NS 2048
#define MPX 65536                // Nz*Nx pixels per batch
#define NKK 4

#define THREADS 256
#define PXT 4                    // pixels per thread
#define TILE_PX (THREADS * PXT)  // 1024 pixels per CTA
#define TILES (MPX / TILE_PX)    // 64 tiles per batch

#define SPLIT 4
#define CPC (NC / SPLIT)         // 32 channels per CTA

#define NBUF 3                   // triple buffer
#define CH_BYTES (NS * NKK * 2)  // 16384 B per fp16 channel row

#define SMEM_PR_OFF   (NBUF * CH_BYTES)
#define SMEM_MBAR_OFF (SMEM_PR_OFF + CPC * 3 * 4)
#define SMEM_BYTES    (SMEM_MBAR_OFF + NBUF * 8)

// Static device scratch (no allocations allowed)
__device__ __half g_rf16[(size_t)NB * NC * NS * NKK];           // 4.2 MB
__device__ float  g_part[(size_t)SPLIT * NB * MPX * NKK];       // 8.4 MB

__device__ __forceinline__ unsigned smem_u32(const void* p) {
    unsigned a;
    asm("{ .reg .u64 t; cvta.to.shared.u64 t, %1; cvt.u32.u64 %0, t; }"
        : "=r"(a) : "l"(p));
    return a;
}
__device__ __forceinline__ void mbar_init(unsigned mbar, unsigned count) {
    asm volatile("mbarrier.init.shared.b64 [%0], %1;" :: "r"(mbar), "r"(count) : "memory");
}
__device__ __forceinline__ void mbar_expect_tx(unsigned mbar, unsigned bytes) {
    asm volatile("mbarrier.arrive.expect_tx.shared.b64 _, [%0], %1;"
                 :: "r"(mbar), "r"(bytes) : "memory");
}
__device__ __forceinline__ void mbar_wait_parity(unsigned mbar, unsigned parity) {
    unsigned done;
    asm volatile(
        "{\n\t"
        ".reg .pred p;\n\t"
        "mbarrier.try_wait.parity.acquire.cta.shared::cta.b64 p, [%1], %2;\n\t"
        "selp.b32 %0, 1, 0, p;\n\t"
        "}"
        : "=r"(done) : "r"(mbar), "r"(parity) : "memory");
    if (!done) {
        asm volatile(
            "{\n\t"
            ".reg .pred P1;\n\t"
            "WAIT_LOOP_%=:\n\t"
            "mbarrier.try_wait.parity.acquire.cta.shared::cta.b64 P1, [%0], %1, 0x989680;\n\t"
            "@P1 bra.uni WAIT_DONE_%=;\n\t"
            "bra.uni WAIT_LOOP_%=;\n\t"
            "WAIT_DONE_%=:\n\t"
            "}"
            :: "r"(mbar), "r"(parity) : "memory");
    }
}
__device__ __forceinline__ void bulk_copy_g2s(unsigned dst_smem, const void* src,
                                              unsigned bytes, unsigned mbar) {
    asm volatile(
        "cp.async.bulk.shared::cta.global.mbarrier::complete_tx::bytes [%0], [%1], %2, [%3];"
        :: "r"(dst_smem), "l"(src), "r"(bytes), "r"(mbar) : "memory");
}
__device__ __forceinline__ void fence_async_shared() {
    asm volatile("fence.proxy.async.shared::cta;" ::: "memory");
}
// PDL primitives
__device__ __forceinline__ void gdc_wait() {
    asm volatile("griddepcontrol.wait;" ::: "memory");
}
__device__ __forceinline__ void gdc_launch_dependents() {
    asm volatile("griddepcontrol.launch_dependents;" ::: "memory");
}

// ---------------------------------------------------------------------------
// Kernel 1: convert rf fp32 -> fp16 scratch. 2 rows per thread.
// ---------------------------------------------------------------------------
__global__ void convert_rf_kernel(const float4* __restrict__ rf4) {
    // Allow the dependent das kernel to launch early; its griddepcontrol.wait
    // still blocks until this grid completes (memory visible).
    gdc_launch_dependents();
    int t = blockIdx.x * blockDim.x + threadIdx.x;   // NB*NC*NS/2 threads
    int idx = t * 2;
    float4 v0 = rf4[idx + 0];
    float4 v1 = rf4[idx + 1];
    uint4 o;
    __half2 h;
    h = __floats2half2_rn(v0.x, v0.y); o.x = *reinterpret_cast<unsigned*>(&h);
    h = __floats2half2_rn(v0.z, v0.w); o.y = *reinterpret_cast<unsigned*>(&h);
    h = __floats2half2_rn(v1.x, v1.y); o.z = *reinterpret_cast<unsigned*>(&h);
    h = __floats2half2_rn(v1.z, v1.w); o.w = *reinterpret_cast<unsigned*>(&h);
    reinterpret_cast<uint4*>(g_rf16)[t] = o;
}

// ---------------------------------------------------------------------------
// Kernel 2: main DAS beamform over a channel slice, writes partial sums.
// TMA bulk fill (one 16KB copy per channel), triple-buffered.
// PDL: prologue (coords/base/mbar init) overlaps the convert kernel; only the
// first TMA fill waits on convert's completion.
// ---------------------------------------------------------------------------
extern __shared__ char smem_raw[];

__global__ __launch_bounds__(THREADS, 4)
void das_beamform_kernel(const float* __restrict__ g,
                         const float* __restrict__ pr,
                         const float* __restrict__ p)
{
    uint2* sbuf = reinterpret_cast<uint2*>(smem_raw);                  // [NBUF][NS]
    float* s_pr = reinterpret_cast<float*>(smem_raw + SMEM_PR_OFF);
    const unsigned mbar0 = smem_u32(smem_raw + SMEM_MBAR_OFF);         // 3 mbarriers

    const int b     = blockIdx.y;
    const int sp    = blockIdx.z;
    const int tile0 = blockIdx.x * TILE_PX;
    const int tid   = threadIdx.x;
    const int c0    = sp * CPC;

    const float c0v = p[b * 4 + 0];
    const float fs  = p[b * 4 + 1];
    const float t0  = p[b * 4 + 2];
    const float scale = fs / c0v;
    const float toff  = t0 * scale;

    // Cache this slice's receiver positions (independent of convert)
    if (tid < CPC * 3)
        s_pr[tid] = pr[((size_t)b * NC + c0) * 3 + tid];

    // mbarrier init (independent of convert)
    if (tid == 0) {
        #pragma unroll
        for (int i = 0; i < NBUF; i++)
            mbar_init(mbar0 + i * 8, 1);
        fence_async_shared();
    }

    // Per-pixel coords + tx base (independent of convert; cold g loads overlap)
    float gx[PXT], gy[PXT], gz[PXT], base[PXT];
    float4 acc[PXT];
#pragma unroll
    for (int q = 0; q < PXT; q++) {
        int m = tile0 + tid + q * THREADS;
        const float* gp = g + ((size_t)b * MPX + m) * 3;
        gx[q] = gp[0];
        gy[q] = gp[1];
        gz[q] = gp[2];
        base[q] = fmaf(scale, gz[q], toff);
        acc[q] = make_float4(0.f, 0.f, 0.f, 0.f);
    }

    // fp16 rf channel rows for this (batch, slice)
    const char* rfb = reinterpret_cast<const char*>(g_rf16) +
                      ((size_t)b * NC + c0) * CH_BYTES;

    __syncthreads();   // mbar init visible before any TMA targets them

    // ---- dependency point: g_rf16 produced by convert ----
    gdc_wait();

    // Issue preload of channels 0,1 (thread 0)
    if (tid == 0) {
        #pragma unroll
        for (int pc = 0; pc < 2; pc++) {
            mbar_expect_tx(mbar0 + pc * 8, CH_BYTES);
            bulk_copy_g2s(smem_u32(sbuf) + pc * CH_BYTES,
                          rfb + (size_t)pc * CH_BYTES, CH_BYTES, mbar0 + pc * 8);
        }
    }

    for (int cc = 0; cc < CPC; cc++) {
        // All threads done with channel cc-1 => buffer (cc+2)%NBUF is free
        __syncthreads();

        if (tid == 0 && cc + 2 < CPC) {
            int nb = (cc + 2) % NBUF;
            fence_async_shared();
            mbar_expect_tx(mbar0 + nb * 8, CH_BYTES);
            bulk_copy_g2s(smem_u32(sbuf) + nb * CH_BYTES,
                          rfb + (size_t)(cc + 2) * CH_BYTES, CH_BYTES, mbar0 + nb * 8);
        }

        // Wait for channel cc's buffer
        mbar_wait_parity(mbar0 + (cc % NBUF) * 8, (cc / NBUF) & 1);

        const uint2* buf = sbuf + (cc % NBUF) * NS;
        const float prx = s_pr[cc * 3 + 0];
        const float pry = s_pr[cc * 3 + 1];
        const float prz = s_pr[cc * 3 + 2];

#pragma unroll
        for (int q = 0; q < PXT; q++) {
            float dx = gx[q] - prx;
            float dy = gy[q] - pry;
            float dz = gz[q] - prz;
            float d2 = fmaf(dx, dx, fmaf(dy, dy, dz * dz));
            float dr = sqrtf(d2);
            float s  = fmaf(scale, dr, base[q]);
            s = fminf(fmaxf(s, 0.0f), (float)(NS - 1));
            int i0 = (int)s;
            i0 = min(i0, NS - 2);
            float w = s - (float)i0;

            uint2 r0 = buf[i0];
            uint2 r1 = buf[i0 + 1];
            float2 a0 = __half22float2(*reinterpret_cast<__half2*>(&r0.x));
            float2 b0 = __half22float2(*reinterpret_cast<__half2*>(&r0.y));
            float2 a1 = __half22float2(*reinterpret_cast<__half2*>(&r1.x));
            float2 b1 = __half22float2(*reinterpret_cast<__half2*>(&r1.y));

            acc[q].x = fmaf(w, a1.x - a0.x, acc[q].x + a0.x);
            acc[q].y = fmaf(w, a1.y - a0.y, acc[q].y + a0.y);
            acc[q].z = fmaf(w, b1.x - b0.x, acc[q].z + b0.x);
            acc[q].w = fmaf(w, b1.y - b0.y, acc[q].w + b0.y);
        }
    }

    // Let the reduce kernel launch while we write partials
    gdc_launch_dependents();

    float4* pp = reinterpret_cast<float4*>(g_part) +
                 ((size_t)sp * NB + b) * MPX + tile0;
#pragma unroll
    for (int q = 0; q < PXT; q++)
        pp[tid + q * THREADS] = acc[q];
}

// ---------------------------------------------------------------------------
// Kernel 3: reduce SPLIT partials into the output. PDL secondary of das.
// ---------------------------------------------------------------------------
__global__ void reduce_kernel(float4* __restrict__ out4) {
    int i = blockIdx.x * blockDim.x + threadIdx.x;   // over NB*MPX float4s
    gdc_wait();   // das partials complete + visible
    const size_t stride = (size_t)NB * MPX;
    const float4* pp = reinterpret_cast<const float4*>(g_part);
    float4 a = pp[i];
    float4 b = pp[i + stride];
    float4 c = pp[i + 2 * stride];
    float4 d = pp[i + 3 * stride];
    float4 r;
    r.x = (a.x + b.x) + (c.x + d.x);
    r.y = (a.y + b.y) + (c.y + d.y);
    r.z = (a.z + b.z) + (c.z + d.z);
    r.w = (a.w + b.w) + (c.w + d.w);
    out4[i] = r;
}

extern "C" void kernel_launch(void* const* d_in, const int* in_sizes, int n_in,
                              void* d_out, int out_size)
{
    const float* rf = (const float*)d_in[0];   // [B, Nc, Ns, K]
    const float* g  = (const float*)d_in[1];   // [B, Nz, Nx, 3]
    const float* pr = (const float*)d_in[2];   // [B, Nc, 3]
    const float* p  = (const float*)d_in[3];   // [B, 4]
    float* out = (float*)d_out;                // [B, Nz, Nx, K]

    cudaFuncSetAttribute(das_beamform_kernel,
                         cudaFuncAttributeMaxDynamicSharedMemorySize, SMEM_BYTES);

    // 1) convert rf to fp16 scratch
    int rows = NB * NC * NS;   // 524288
    convert_rf_kernel<<<rows / 2 / 256, 256>>>((const float4*)rf);

    // 2) beamform — PDL secondary: launches under convert, waits on data
    {
        cudaLaunchConfig_t cfg = {};
        cfg.gridDim = dim3(TILES, NB, SPLIT);
        cfg.blockDim = dim3(THREADS, 1, 1);
        cfg.dynamicSmemBytes = SMEM_BYTES;
        cudaLaunchAttribute attr[1];
        attr[0].id = cudaLaunchAttributeProgrammaticStreamSerialization;
        attr[0].val.programmaticStreamSerializationAllowed = 1;
        cfg.attrs = attr;
        cfg.numAttrs = 1;
        cudaLaunchKernelEx(&cfg, das_beamform_kernel, g, pr, p);
    }

    // 3) reduce — PDL secondary of das
    {
        int n4 = NB * MPX;     // 131072 float4s
        cudaLaunchConfig_t cfg = {};
        cfg.gridDim = dim3(n4 / 256, 1, 1);
        cfg.blockDim = dim3(256, 1, 1);
        cudaLaunchAttribute attr[1];
        attr[0].id = cudaLaunchAttributeProgrammaticStreamSerialization;
        attr[0].val.programmaticStreamSerializationAllowed = 1;
        cfg.attrs = attr;
        cfg.numAttrs = 1;
        cudaLaunchKernelEx(&cfg, reduce_kernel, (float4*)out);
    }
}